// round 5
// baseline (speedup 1.0000x reference)
#include <cuda_runtime.h>
#include <cuda_bf16.h>

#define NB   8
#define NN   256
#define NIN  16
#define NH   32
#define TILE 16
#define NT   (NN/TILE)          // 16
#define NTRI (NT*(NT+1)/2)      // 136
#define NBLK2 (NB*NTRI)         // 1088

typedef unsigned long long ull;

// ---- packed f32x2 helpers ----
__device__ __forceinline__ ull packf2(float lo, float hi) {
    ull r; asm("mov.b64 %0, {%1, %2};" : "=l"(r) : "f"(lo), "f"(hi)); return r;
}
__device__ __forceinline__ ull packdup(float v) {
    ull r; asm("mov.b64 %0, {%1, %1};" : "=l"(r) : "f"(v)); return r;
}
__device__ __forceinline__ ull ffma2(ull a, ull b, ull c) {
    ull d; asm("fma.rn.f32x2 %0, %1, %2, %3;" : "=l"(d) : "l"(a), "l"(b), "l"(c)); return d;
}
__device__ __forceinline__ float2 unpackf2(ull v) {
    float lo, hi; asm("mov.b64 {%0, %1}, %2;" : "=f"(lo), "=f"(hi) : "l"(v));
    return make_float2(lo, hi);
}
__device__ __forceinline__ float2 bf2f(unsigned int u) {
    return __bfloat1622float2(*reinterpret_cast<__nv_bfloat162*>(&u));
}
__device__ __forceinline__ unsigned int f2bf(float a, float b) {
    __nv_bfloat162 h = __floats2bfloat162_rn(a, b);
    return *reinterpret_cast<unsigned int*>(&h);
}

// ---- scratch (device globals) ----
// G pair form of layer-2 einsum term: G1=G[i,j,s], G2=G[j,i,s] (bf16)
__device__ __nv_bfloat16 g_G1[(size_t)NB*NTRI*256*NH];   // 17.8 MB
__device__ __nv_bfloat16 g_G2[(size_t)NB*NTRI*256*NH];   // 17.8 MB
__device__ float g_R1[NB*NN*NH];
__device__ float g_Dg1[NB*NN*NH];
__device__ float g_T1[NB*NH];
__device__ float g_rowpart[(size_t)NB*NTRI*1024];        // per-tile rowsum partials [I:512 | J:512]
__device__ float g_diag[NB*NN*NH];                       // h1 diagonal (f32)
__device__ float g_R2[NB*NN*NH];
__device__ float g_Dg2[NB*NN*NH];
__device__ float g_T2[NB*NH];
__device__ float g_part[(size_t)NBLK2*NH];

// ============================================================
// P1: per-batch positional precompute for layer 1 (8 blocks).
// ============================================================
__global__ void __launch_bounds__(256) p1_kernel(const float* __restrict__ x,
                                                 const float* __restrict__ W1,
                                                 const float* __restrict__ b1) {
    int b = blockIdx.x, tid = threadIdx.x;
    __shared__ float xs[NN*17];
    __shared__ float Ws[NH*NH*5];
    __shared__ float Ss[NIN];
    __shared__ float red[8*NIN];

    const float4* xg = (const float4*)(x + (size_t)b*NN*NIN);
    for (int e = tid; e < NN*NIN/4; e += 256) {
        float4 v = xg[e];
        int r = e >> 2, c0 = (e & 3)*4;
        float* dst = xs + r*17 + c0;
        dst[0] = v.x; dst[1] = v.y; dst[2] = v.z; dst[3] = v.w;
    }
    for (int e = tid; e < NH*NH*5; e += 256) Ws[e] = W1[e];
    __syncthreads();

    float xv[NIN];
    #pragma unroll
    for (int d = 0; d < NIN; d++) xv[d] = xs[tid*17 + d];

    int lane = tid & 31, w = tid >> 5;
    #pragma unroll
    for (int d = 0; d < NIN; d++) {
        float v = xv[d];
        #pragma unroll
        for (int o = 16; o; o >>= 1) v += __shfl_xor_sync(0xffffffffu, v, o);
        if (lane == 0) red[w*NIN + d] = v;
    }
    __syncthreads();
    if (tid < NIN) {
        float s = 0.f;
        #pragma unroll
        for (int w2 = 0; w2 < 8; w2++) s += red[w2*NIN + tid];
        Ss[tid] = s;
    }
    __syncthreads();

    const float inv_n = 1.0f/(float)NN, inv_n2 = inv_n*inv_n;
    int i = tid;
    for (int s = 0; s < NH; s++) {
        float r = 0.f, dg = 0.f;
        #pragma unroll
        for (int d = 0; d < NIN; d++) {
            const float* wd  = &Ws[(d*NH + s)*5];
            const float* wd2 = &Ws[((NIN+d)*NH + s)*5];
            r  += xv[d]*wd[3] + xv[d]*Ss[d]*wd2[3];
            dg += xv[d]*(wd[0] + wd[1] + wd[2]) + xv[d]*xv[d]*wd2[2];
        }
        g_R1 [((size_t)b*NN + i)*NH + s] = r*inv_n;
        g_Dg1[((size_t)b*NN + i)*NH + s] = dg;
    }
    if (tid < NH) {
        int s = tid;
        float t = b1[s];
        #pragma unroll
        for (int d = 0; d < NIN; d++) {
            t += Ss[d]*inv_n2       * Ws[(d*NH + s)*5 + 4];
            t += Ss[d]*Ss[d]*inv_n2 * Ws[((NIN+d)*NH + s)*5 + 4];
        }
        g_T1[b*NH + s] = t;
    }
}

// ============================================================
// K1F: fused layer-1 + layer-2 GEMM per unordered pair tile.
// Phase 1: c1/c2 (layer-1) -> ap/am bf16 into SMEM + rowparts + diag.
// Phase 2: GEMM (ap,am) x (Wp,Wm) -> G1/G2 bf16 to global.
// grid (NTRI, NB), block 256.
// ============================================================
__global__ void __launch_bounds__(256, 2) k1f_kernel(const float* __restrict__ x,
                                                     const float* __restrict__ W1,
                                                     const float* __restrict__ W2) {
    extern __shared__ char smraw[];
    ull*   Wa2 = (ull*)smraw;                 // 256
    ull*   Wp2 = Wa2 + 256;                   // 512
    ull*   Wm2 = Wp2 + 512;                   // 512
    float* xi   = (float*)(Wm2 + 512);        // 272
    float* xj   = xi + 272;                   // 272
    float* posI = xj + 272;                   // 512
    float* posJ = posI + 512;                 // 512
    float* dgs  = posJ + 512;                 // 512
    float* t1s  = dgs + 512;                  // 32
    float* red  = t1s + 32;                   // 256*36
    unsigned int* apS = (unsigned int*)(red + 256*36);  // 256*17
    unsigned int* amS = apS + 256*17;                   // 256*17

    int tp = blockIdx.x, b = blockIdx.y, t = threadIdx.x;
    int ti = 0, rr0 = tp;
    while (rr0 >= NT - ti) { rr0 -= NT - ti; ti++; }
    int tj = ti + rr0;
    int I = ti*TILE, J = tj*TILE;
    int ii = t >> 4, jj = t & 15;
    bool isdiag = (ti == tj);

    {
        int r = t >> 4, c = t & 15;
        xi[r*17 + c] = x[(size_t)b*NN*NIN + (I+r)*NIN + c];
        xj[r*17 + c] = x[(size_t)b*NN*NIN + (J+r)*NIN + c];
    }
    {
        int d = t >> 4, k = t & 15, s0 = 2*k;
        float a0 = W1[((NIN+d)*NH + s0  )*5 + 0] + W1[((NIN+d)*NH + s0  )*5 + 1];
        float a1 = W1[((NIN+d)*NH + s0+1)*5 + 0] + W1[((NIN+d)*NH + s0+1)*5 + 1];
        Wa2[t] = packf2(a0, a1);
    }
    for (int e = t; e < 512; e += 256) {
        int tt = e >> 4, k = e & 15, s0 = 2*k;
        float w00 = W2[(tt*NH + s0  )*5 + 0], w01 = W2[(tt*NH + s0  )*5 + 1];
        float w10 = W2[(tt*NH + s0+1)*5 + 0], w11 = W2[(tt*NH + s0+1)*5 + 1];
        Wp2[e] = packf2(w00 + w01, w10 + w11);
        Wm2[e] = packf2(w00 - w01, w10 - w11);
    }
    for (int e = t; e < 512; e += 256) {
        int r = e >> 5, s = e & 31;
        posI[e] = g_R1 [((size_t)b*NN + I + r)*NH + s];
        posJ[e] = g_R1 [((size_t)b*NN + J + r)*NH + s];
        dgs[e]  = g_Dg1[((size_t)b*NN + I + r)*NH + s];
    }
    if (t < NH) t1s[t] = g_T1[b*NH + t];
    __syncthreads();

    // ---- phase 1: layer-1 ----
    float z[NIN];
    #pragma unroll
    for (int d = 0; d < NIN; d++) z[d] = xi[ii*17 + d] * xj[jj*17 + d];

    ull acc2[16];
    #pragma unroll
    for (int k = 0; k < 16; k++) acc2[k] = 0ull;
    #pragma unroll
    for (int d = 0; d < NIN; d++) {
        ull zd = packdup(z[d]);
        const ulonglong2* w = (const ulonglong2*)(Wa2 + d*16);
        #pragma unroll
        for (int k4 = 0; k4 < 8; k4++) {
            ulonglong2 ww = w[k4];
            acc2[2*k4]   = ffma2(zd, ww.x, acc2[2*k4]);
            acc2[2*k4+1] = ffma2(zd, ww.y, acc2[2*k4+1]);
        }
    }

    bool dgflag = isdiag && (ii == jj);
    float c1[NH], c2[NH];
    #pragma unroll
    for (int k = 0; k < 16; k++) {
        float2 m = unpackf2(acc2[k]);
        int s0 = 2*k, s1 = 2*k + 1;
        float e0 = dgflag ? dgs[ii*NH + s0] : 0.f;
        float e1 = dgflag ? dgs[ii*NH + s1] : 0.f;
        c1[s0] = fmaxf(m.x + posI[ii*NH + s0] + t1s[s0] + e0, 0.f);
        c1[s1] = fmaxf(m.y + posI[ii*NH + s1] + t1s[s1] + e1, 0.f);
        c2[s0] = fmaxf(m.x + posJ[jj*NH + s0] + t1s[s0] + e0, 0.f);
        c2[s1] = fmaxf(m.y + posJ[jj*NH + s1] + t1s[s1] + e1, 0.f);
    }

    // pair form into SMEM (bf16)
    #pragma unroll
    for (int k = 0; k < 16; k++) {
        apS[t*17 + k] = f2bf(c1[2*k] + c2[2*k], c1[2*k+1] + c2[2*k+1]);
        amS[t*17 + k] = f2bf(c1[2*k] - c2[2*k], c1[2*k+1] - c2[2*k+1]);
    }
    if (dgflag) {
        #pragma unroll
        for (int s = 0; s < NH; s++)
            g_diag[((size_t)b*NN + I + ii)*NH + s] = c1[s];
    }

    // rowsum partials: pass 1 (c1 -> side I)
    {
        float4* rr = (float4*)(red + t*36);
        #pragma unroll
        for (int k = 0; k < 8; k++)
            rr[k] = make_float4(c1[4*k], c1[4*k+1], c1[4*k+2], c1[4*k+3]);
    }
    __syncthreads();
    for (int c = t; c < 512; c += 256) {
        int r = c >> 5, s = c & 31;
        float v = 0.f;
        #pragma unroll
        for (int q = 0; q < 16; q++) v += red[(r*16 + q)*36 + s];
        g_rowpart[(size_t)(b*NTRI + tp)*1024 + c] = v;
    }
    __syncthreads();
    // pass 2 (c2 -> side J)
    {
        float4* rr = (float4*)(red + t*36);
        #pragma unroll
        for (int k = 0; k < 8; k++)
            rr[k] = make_float4(c2[4*k], c2[4*k+1], c2[4*k+2], c2[4*k+3]);
    }
    __syncthreads();
    for (int c = t; c < 512; c += 256) {
        int r = c >> 5, s = c & 31;   // r = jj
        float v = 0.f;
        #pragma unroll
        for (int q = 0; q < 16; q++) v += red[(q*16 + r)*36 + s];
        g_rowpart[(size_t)(b*NTRI + tp)*1024 + 512 + c] = v;
    }
    __syncthreads();   // apS/amS globally visible; red done

    // ---- phase 2: layer-2 GEMM (2 pairs x 16 s per thread) ----
    int duo = t & 127, sh = t >> 7;
    const unsigned int* pa = apS + duo*17;
    const unsigned int* ma = amS + duo*17;
    const unsigned int* pb = apS + (duo + 128)*17;
    const unsigned int* mb = amS + (duo + 128)*17;

    ull aPA[8], aMA[8], aPB[8], aMB[8];
    #pragma unroll
    for (int k = 0; k < 8; k++) { aPA[k]=0; aMA[k]=0; aPB[k]=0; aMB[k]=0; }

    #pragma unroll 4
    for (int w = 0; w < 16; w++) {
        float2 fpA = bf2f(pa[w]);
        float2 fmA = bf2f(ma[w]);
        float2 fpB = bf2f(pb[w]);
        float2 fmB = bf2f(mb[w]);
        #pragma unroll
        for (int h = 0; h < 2; h++) {
            int tt = 2*w + h;
            ull xpA = packdup(h ? fpA.y : fpA.x);
            ull xmA = packdup(h ? fmA.y : fmA.x);
            ull xpB = packdup(h ? fpB.y : fpB.x);
            ull xmB = packdup(h ? fmB.y : fmB.x);
            const ulonglong2* wp = (const ulonglong2*)(Wp2 + tt*16 + sh*8);
            const ulonglong2* wm = (const ulonglong2*)(Wm2 + tt*16 + sh*8);
            #pragma unroll
            for (int q = 0; q < 4; q++) {
                ulonglong2 wwp = wp[q];
                aPA[2*q]   = ffma2(xpA, wwp.x, aPA[2*q]);
                aPA[2*q+1] = ffma2(xpA, wwp.y, aPA[2*q+1]);
                aPB[2*q]   = ffma2(xpB, wwp.x, aPB[2*q]);
                aPB[2*q+1] = ffma2(xpB, wwp.y, aPB[2*q+1]);
                ulonglong2 wwm = wm[q];
                aMA[2*q]   = ffma2(xmA, wwm.x, aMA[2*q]);
                aMA[2*q+1] = ffma2(xmA, wwm.y, aMA[2*q+1]);
                aMB[2*q]   = ffma2(xmB, wwm.x, aMB[2*q]);
                aMB[2*q+1] = ffma2(xmB, wwm.y, aMB[2*q+1]);
            }
        }
    }

    // convert to G1/G2 (element forms) and store bf16
    unsigned int o1A[8], o2A[8], o1B[8], o2B[8];
    #pragma unroll
    for (int k = 0; k < 8; k++) {
        float2 P = unpackf2(aPA[k]), M = unpackf2(aMA[k]);
        o1A[k] = f2bf(0.5f*(P.x + M.x), 0.5f*(P.y + M.y));
        o2A[k] = f2bf(0.5f*(P.x - M.x), 0.5f*(P.y - M.y));
        float2 Pb = unpackf2(aPB[k]), Mb = unpackf2(aMB[k]);
        o1B[k] = f2bf(0.5f*(Pb.x + Mb.x), 0.5f*(Pb.y + Mb.y));
        o2B[k] = f2bf(0.5f*(Pb.x - Mb.x), 0.5f*(Pb.y - Mb.y));
    }
    size_t base = (size_t)(b*NTRI + tp)*256;
    {
        uint4* d1 = (uint4*)(g_G1 + (base + duo)*NH + sh*16);
        d1[0] = make_uint4(o1A[0], o1A[1], o1A[2], o1A[3]);
        d1[1] = make_uint4(o1A[4], o1A[5], o1A[6], o1A[7]);
        uint4* d2 = (uint4*)(g_G2 + (base + duo)*NH + sh*16);
        d2[0] = make_uint4(o2A[0], o2A[1], o2A[2], o2A[3]);
        d2[1] = make_uint4(o2A[4], o2A[5], o2A[6], o2A[7]);
        uint4* e1 = (uint4*)(g_G1 + (base + duo + 128)*NH + sh*16);
        e1[0] = make_uint4(o1B[0], o1B[1], o1B[2], o1B[3]);
        e1[1] = make_uint4(o1B[4], o1B[5], o1B[6], o1B[7]);
        uint4* e2 = (uint4*)(g_G2 + (base + duo + 128)*NH + sh*16);
        e2[0] = make_uint4(o2B[0], o2B[1], o2B[2], o2B[3]);
        e2[1] = make_uint4(o2B[4], o2B[5], o2B[6], o2B[7]);
    }
}

// ============================================================
// P2: gather rowsums from tile partials, compute layer-2 positional terms.
// ============================================================
__global__ void __launch_bounds__(256) p2_kernel(const float* __restrict__ W2,
                                                 const float* __restrict__ b2) {
    int b = blockIdx.x, tid = threadIdx.x;
    __shared__ float Ws[NH*NH*5];
    __shared__ float red[8*NH];
    __shared__ float tot[NH];
    for (int e = tid; e < NH*NH*5; e += 256) Ws[e] = W2[e];

    int ti = tid >> 4, ii = tid & 15;
    float ra[NH];
    #pragma unroll
    for (int s = 0; s < NH; s++) ra[s] = 0.f;

    for (int tj = ti; tj < NT; tj++) {
        int tp = ti*NT - ti*(ti-1)/2 + (tj - ti);
        const float4* p4 = (const float4*)(g_rowpart + (size_t)(b*NTRI + tp)*1024 + ii*NH);
        #pragma unroll
        for (int q = 0; q < 8; q++) {
            float4 v = p4[q];
            ra[4*q] += v.x; ra[4*q+1] += v.y; ra[4*q+2] += v.z; ra[4*q+3] += v.w;
        }
    }
    for (int tk = 0; tk < ti; tk++) {
        int tp = tk*NT - tk*(tk-1)/2 + (ti - tk);
        const float4* p4 = (const float4*)(g_rowpart + (size_t)(b*NTRI + tp)*1024 + 512 + ii*NH);
        #pragma unroll
        for (int q = 0; q < 8; q++) {
            float4 v = p4[q];
            ra[4*q] += v.x; ra[4*q+1] += v.y; ra[4*q+2] += v.z; ra[4*q+3] += v.w;
        }
    }

    float dv[NH];
    {
        const float* dp = g_diag + ((size_t)b*NN + tid)*NH;
        #pragma unroll
        for (int s = 0; s < NH; s++) dv[s] = dp[s];
    }
    __syncthreads();

    int lane = tid & 31, w = tid >> 5;
    #pragma unroll
    for (int s = 0; s < NH; s++) {
        float v = ra[s];
        #pragma unroll
        for (int o = 16; o; o >>= 1) v += __shfl_xor_sync(0xffffffffu, v, o);
        if (lane == 0) red[w*NH + s] = v;
    }
    __syncthreads();
    if (tid < NH) {
        float s = 0.f;
        #pragma unroll
        for (int w2 = 0; w2 < 8; w2++) s += red[w2*NH + tid];
        tot[tid] = s * (1.0f/((float)NN*(float)NN));
    }
    __syncthreads();

    const float inv_n = 1.0f/(float)NN;
    for (int s = 0; s < NH; s++) {
        float r2 = 0.f, dg2 = 0.f;
        #pragma unroll
        for (int q = 0; q < NH; q++) {
            r2  = fmaf(ra[q]*inv_n, Ws[(q*NH + s)*5 + 3], r2);
            dg2 = fmaf(dv[q],       Ws[(q*NH + s)*5 + 2], dg2);
        }
        g_R2 [((size_t)b*NN + tid)*NH + s] = r2;
        g_Dg2[((size_t)b*NN + tid)*NH + s] = dg2;
    }
    if (tid < NH) {
        int s = tid;
        float t2 = b2[s];
        #pragma unroll
        for (int q = 0; q < NH; q++) t2 = fmaf(tot[q], Ws[(q*NH + s)*5 + 4], t2);
        g_T2[b*NH + s] = t2;
    }
}

// ============================================================
// K2B: lean streaming epilogue — load G1/G2, add positional, relu, reduce.
// grid (NTRI, NB), block 256 (thread = pair).
// ============================================================
__global__ void __launch_bounds__(256) k2b_kernel() {
    __shared__ float bs1[512], bs2[512], dgI[512];
    __shared__ float red[256*36];
    __shared__ float part2[8*NH];

    int tp = blockIdx.x, b = blockIdx.y, t = threadIdx.x;
    int ti = 0, rr0 = tp;
    while (rr0 >= NT - ti) { rr0 -= NT - ti; ti++; }
    int tj = ti + rr0;
    int I = ti*TILE, J = tj*TILE;
    int bid = b*NTRI + tp;
    bool isdiag = (ti == tj);

    for (int e = t; e < 512; e += 256) {
        int r = e >> 5, s = e & 31;
        float t2v = g_T2[b*NH + s];
        bs1[e] = g_R2[((size_t)b*NN + I + r)*NH + s] + t2v;
        bs2[e] = g_R2[((size_t)b*NN + J + r)*NH + s] + t2v;
        dgI[e] = g_Dg2[((size_t)b*NN + I + r)*NH + s];
    }
    __syncthreads();

    int ii = t >> 4, jj = t & 15;
    size_t off = ((size_t)bid*256 + t)*NH;
    const uint4* q1 = (const uint4*)(g_G1 + off);
    const uint4* q2 = (const uint4*)(g_G2 + off);

    float cs[NH];
    #pragma unroll
    for (int v4 = 0; v4 < 4; v4++) {
        uint4 a = q1[v4], bq = q2[v4];
        unsigned int ua[4] = {a.x, a.y, a.z, a.w};
        unsigned int ub[4] = {bq.x, bq.y, bq.z, bq.w};
        #pragma unroll
        for (int u = 0; u < 4; u++) {
            int s0 = v4*8 + 2*u;
            float2 f1 = bf2f(ua[u]);
            float2 f2 = bf2f(ub[u]);
            #pragma unroll
            for (int h = 0; h < 2; h++) {
                int s = s0 + h;
                float g1 = h ? f1.y : f1.x;
                float g2 = h ? f2.y : f2.x;
                float b1v = bs1[ii*NH + s];
                if (isdiag && ii == jj) b1v += dgI[ii*NH + s];
                float c1 = fmaxf(g1 + b1v, 0.f);
                float c2 = fmaxf(g2 + bs2[jj*NH + s], 0.f);
                float v = c1 + c2;
                if (isdiag) v = (ii < jj) ? (c1 + c2) : ((ii == jj) ? c1 : 0.f);
                cs[s] = v;
            }
        }
    }

    {
        float4* rr = (float4*)(red + t*36);
        #pragma unroll
        for (int k = 0; k < 8; k++)
            rr[k] = make_float4(cs[4*k], cs[4*k+1], cs[4*k+2], cs[4*k+3]);
    }
    __syncthreads();
    {
        int s = t & 31, c = t >> 5;
        float tsum = 0.f;
        #pragma unroll
        for (int r = 0; r < 32; r++) tsum += red[(c*32 + r)*36 + s];
        part2[c*NH + s] = tsum;
    }
    __syncthreads();
    if (t < NH) {
        float p = 0.f;
        #pragma unroll
        for (int c = 0; c < 8; c++) p += part2[c*NH + t];
        g_part[(size_t)bid*NH + t] = p;
    }
}

// ============================================================
// Final: parallel partial reduce + MLP 32->128->128->1.
// ============================================================
__global__ void __launch_bounds__(256) fin_kernel(const float* __restrict__ D1,
                                                  const float* __restrict__ db1,
                                                  const float* __restrict__ D2,
                                                  const float* __restrict__ db2,
                                                  const float* __restrict__ D3,
                                                  const float* __restrict__ db3,
                                                  float* __restrict__ out) {
    int b = blockIdx.x, tid = threadIdx.x;
    __shared__ float pp[8*NH];
    __shared__ float p[NH];
    __shared__ float m1[128];
    __shared__ float h2p[256];
    __shared__ float m2[128];
    __shared__ float wr[4];

    {
        int s = tid & 31, c = tid >> 5;
        float a = 0.f;
        #pragma unroll 4
        for (int k = c; k < NTRI; k += 8) a += g_part[(size_t)(b*NTRI + k)*NH + s];
        pp[tid] = a;
    }
    __syncthreads();
    if (tid < NH) {
        float t = 0.f;
        #pragma unroll
        for (int c = 0; c < 8; c++) t += pp[c*NH + tid];
        p[tid] = fmaxf(t, 0.f);
    }
    __syncthreads();
    if (tid < 128) {
        float a = db1[tid];
        #pragma unroll
        for (int q = 0; q < NH; q++) a = fmaf(p[q], D1[q*128 + tid], a);
        m1[tid] = fmaxf(a, 0.f);
    }
    __syncthreads();
    {
        int o = tid & 127, half = tid >> 7;
        float a = 0.f;
        #pragma unroll 16
        for (int e = half*64; e < half*64 + 64; e++)
            a = fmaf(m1[e], D2[e*128 + o], a);
        h2p[tid] = a;
    }
    __syncthreads();
    if (tid < 128) m2[tid] = fmaxf(h2p[tid] + h2p[128 + tid] + db2[tid], 0.f);
    __syncthreads();
    if (tid < 128) {
        float v = m2[tid] * D3[tid];
        #pragma unroll
        for (int o = 16; o; o >>= 1) v += __shfl_xor_sync(0xffffffffu, v, o);
        if ((tid & 31) == 0) wr[tid >> 5] = v;
    }
    __syncthreads();
    if (tid == 0) out[b] = wr[0] + wr[1] + wr[2] + wr[3] + db3[0];
}

extern "C" void kernel_launch(void* const* d_in, const int* in_sizes, int n_in,
                              void* d_out, int out_size) {
    const float* x   = (const float*)d_in[0];
    const float* W1  = (const float*)d_in[1];
    const float* b1  = (const float*)d_in[2];
    const float* W2  = (const float*)d_in[3];
    const float* b2  = (const float*)d_in[4];
    const float* D1  = (const float*)d_in[5];
    const float* db1 = (const float*)d_in[6];
    const float* D2  = (const float*)d_in[7];
    const float* db2 = (const float*)d_in[8];
    const float* D3  = (const float*)d_in[9];
    const float* db3 = (const float*)d_in[10];
    float* out = (float*)d_out;

    // k1f dynamic smem: Wa2(2048)+Wp2(4096)+Wm2(4096)+xi/xj(2176)+pos(6144)
    //                   +t1s(128)+red(36864)+apS/amS(34816) = 90368
    size_t k1f_smem = 90368;
    cudaFuncSetAttribute(k1f_kernel, cudaFuncAttributeMaxDynamicSharedMemorySize,
                         (int)k1f_smem);

    p1_kernel<<<NB, 256>>>(x, W1, b1);
    k1f_kernel<<<dim3(NTRI, NB), 256, k1f_smem>>>(x, W1, W2);
    p2_kernel<<<NB, 256>>>(W2, b2);
    k2b_kernel<<<dim3(NTRI, NB), 256>>>();
    fin_kernel<<<NB, 256>>>(D1, db1, D2, db2, D3, db3, out);
}

// round 7
// speedup vs baseline: 1.1013x; 1.1013x over previous
#include <cuda_runtime.h>
#include <cuda_bf16.h>
#include <cstdint>

#define NB   8
#define NN   256
#define NIN  16
#define NH   32
#define TILE 16
#define NT   (NN/TILE)          // 16
#define NTRI (NT*(NT+1)/2)      // 136
#define NBLK2 (NB*NTRI)         // 1088

typedef unsigned long long ull;

// ---- packed f32x2 helpers ----
__device__ __forceinline__ ull packf2(float lo, float hi) {
    ull r; asm("mov.b64 %0, {%1, %2};" : "=l"(r) : "f"(lo), "f"(hi)); return r;
}
__device__ __forceinline__ ull packdup(float v) {
    ull r; asm("mov.b64 %0, {%1, %1};" : "=l"(r) : "f"(v)); return r;
}
__device__ __forceinline__ ull ffma2(ull a, ull b, ull c) {
    ull d; asm("fma.rn.f32x2 %0, %1, %2, %3;" : "=l"(d) : "l"(a), "l"(b), "l"(c)); return d;
}
__device__ __forceinline__ float2 unpackf2(ull v) {
    float lo, hi; asm("mov.b64 {%0, %1}, %2;" : "=f"(lo), "=f"(hi) : "l"(v));
    return make_float2(lo, hi);
}
__device__ __forceinline__ float2 bf2f(unsigned int u) {
    return __bfloat1622float2(*reinterpret_cast<__nv_bfloat162*>(&u));
}
__device__ __forceinline__ unsigned int f2bf(float a, float b) {
    __nv_bfloat162 h = __floats2bfloat162_rn(a, b);
    return *reinterpret_cast<unsigned int*>(&h);
}

// ---- scratch (device globals) ----
__device__ __nv_bfloat16 g_G1[(size_t)NB*NTRI*256*NH];   // 17.8 MB
__device__ __nv_bfloat16 g_G2[(size_t)NB*NTRI*256*NH];   // 17.8 MB
__device__ float g_R1[NB*NN*NH];
__device__ float g_Dg1[NB*NN*NH];
__device__ float g_T1[NB*NH];
__device__ float g_rowpart[(size_t)NB*NTRI*1024];
__device__ float g_diag[NB*NN*NH];
__device__ float g_R2[NB*NN*NH];
__device__ float g_Dg2[NB*NN*NH];
__device__ float g_T2[NB*NH];
__device__ float g_totp[NB*NT*NH];
__device__ float g_part[(size_t)NBLK2*NH];

// ============================================================
// P1: per-batch positional precompute for layer 1.
// ============================================================
__global__ void __launch_bounds__(256) p1_kernel(const float* __restrict__ x,
                                                 const float* __restrict__ W1,
                                                 const float* __restrict__ b1) {
    int b = blockIdx.x, tid = threadIdx.x;
    __shared__ float xs[NN*17];
    __shared__ float Ws[NH*NH*5];
    __shared__ float Ss[NIN];
    __shared__ float red[8*NIN];

    const float4* xg = (const float4*)(x + (size_t)b*NN*NIN);
    for (int e = tid; e < NN*NIN/4; e += 256) {
        float4 v = xg[e];
        int r = e >> 2, c0 = (e & 3)*4;
        float* dst = xs + r*17 + c0;
        dst[0] = v.x; dst[1] = v.y; dst[2] = v.z; dst[3] = v.w;
    }
    for (int e = tid; e < NH*NH*5; e += 256) Ws[e] = W1[e];
    __syncthreads();

    float xv[NIN];
    #pragma unroll
    for (int d = 0; d < NIN; d++) xv[d] = xs[tid*17 + d];

    int lane = tid & 31, w = tid >> 5;
    #pragma unroll
    for (int d = 0; d < NIN; d++) {
        float v = xv[d];
        #pragma unroll
        for (int o = 16; o; o >>= 1) v += __shfl_xor_sync(0xffffffffu, v, o);
        if (lane == 0) red[w*NIN + d] = v;
    }
    __syncthreads();
    if (tid < NIN) {
        float s = 0.f;
        #pragma unroll
        for (int w2 = 0; w2 < 8; w2++) s += red[w2*NIN + tid];
        Ss[tid] = s;
    }
    __syncthreads();

    const float inv_n = 1.0f/(float)NN, inv_n2 = inv_n*inv_n;
    int i = tid;
    for (int s = 0; s < NH; s++) {
        float r = 0.f, dg = 0.f;
        #pragma unroll
        for (int d = 0; d < NIN; d++) {
            const float* wd  = &Ws[(d*NH + s)*5];
            const float* wd2 = &Ws[((NIN+d)*NH + s)*5];
            r  += xv[d]*wd[3] + xv[d]*Ss[d]*wd2[3];
            dg += xv[d]*(wd[0] + wd[1] + wd[2]) + xv[d]*xv[d]*wd2[2];
        }
        g_R1 [((size_t)b*NN + i)*NH + s] = r*inv_n;
        g_Dg1[((size_t)b*NN + i)*NH + s] = dg;
    }
    if (tid < NH) {
        int s = tid;
        float t = b1[s];
        #pragma unroll
        for (int d = 0; d < NIN; d++) {
            t += Ss[d]*inv_n2       * Ws[(d*NH + s)*5 + 4];
            t += Ss[d]*Ss[d]*inv_n2 * Ws[((NIN+d)*NH + s)*5 + 4];
        }
        g_T1[b*NH + s] = t;
    }
}

// ============================================================
// K1F: fused layer-1 + layer-2 GEMM. 512 threads = (pair p, s-half sh).
// Phase 1: layer-1 -> ap/am bf16 in SMEM.
// Phase 2 (one sync later): rowsum partials + diag from SMEM, and the
// layer-2 GEMM -> G1/G2 bf16 to global.
// ============================================================
__global__ void __launch_bounds__(512, 2) k1f_kernel(const float* __restrict__ x,
                                                     const float* __restrict__ W1,
                                                     const float* __restrict__ W2) {
    extern __shared__ __align__(16) char smraw[];
    ull*   Wa2 = (ull*)smraw;                       // 256  @0
    ull*   Wp2 = Wa2 + 256;                         // 512  @2048
    ull*   Wm2 = Wp2 + 512;                         // 512  @6144
    float* xi   = (float*)(Wm2 + 512);              // 272  @10240
    float* xj   = xi + 272;                         // 272  @11328
    float* posI = xj + 272;                         // 512  @12416
    float* posJ = posI + 512;                       // 512  @14464
    float* dgs  = posJ + 512;                       // 512  @16512
    float* t1s  = dgs + 512;                        // 32   @18560
    unsigned int* apS = (unsigned int*)(t1s + 32);  // 256*17 @18688
    unsigned int* amS = apS + 256*17;               // 256*17 @36096
    // total 53504 B

    int tp = blockIdx.x, b = blockIdx.y, t = threadIdx.x;
    int ti = 0, rr0 = tp;
    while (rr0 >= NT - ti) { rr0 -= NT - ti; ti++; }
    int tj = ti + rr0;
    int I = ti*TILE, J = tj*TILE;
    int bid = b*NTRI + tp;
    bool isdiag = (ti == tj);

    // ---- staging ----
    if (t < 256) {
        int r = t >> 4, c = t & 15;
        xi[r*17 + c] = x[(size_t)b*NN*NIN + (I+r)*NIN + c];
        int d = r, k = c, s0 = 2*k;
        float a0 = W1[((NIN+d)*NH + s0  )*5 + 0] + W1[((NIN+d)*NH + s0  )*5 + 1];
        float a1 = W1[((NIN+d)*NH + s0+1)*5 + 0] + W1[((NIN+d)*NH + s0+1)*5 + 1];
        Wa2[t] = packf2(a0, a1);
    } else {
        int e = t - 256;
        int r = e >> 4, c = e & 15;
        xj[r*17 + c] = x[(size_t)b*NN*NIN + (J+r)*NIN + c];
    }
    {
        int e = t;   // 0..511
        int tt = e >> 4, k = e & 15, s0 = 2*k;
        float w00 = W2[(tt*NH + s0  )*5 + 0], w01 = W2[(tt*NH + s0  )*5 + 1];
        float w10 = W2[(tt*NH + s0+1)*5 + 0], w11 = W2[(tt*NH + s0+1)*5 + 1];
        Wp2[e] = packf2(w00 + w01, w10 + w11);
        Wm2[e] = packf2(w00 - w01, w10 - w11);
    }
    {
        int e = t;
        int r = e >> 5, s = e & 31;
        posI[e] = g_R1 [((size_t)b*NN + I + r)*NH + s];
        posJ[e] = g_R1 [((size_t)b*NN + J + r)*NH + s];
        dgs[e]  = g_Dg1[((size_t)b*NN + I + r)*NH + s];
    }
    if (t < NH) t1s[t] = g_T1[b*NH + t];
    __syncthreads();

    // ---- phase 1: layer-1 for 16 s-values ----
    int p = t & 255, sh = t >> 8;
    int ii = p >> 4, jj = p & 15;
    int sb = sh*16;
    bool dgflag = isdiag && (ii == jj);

    ull acc2[8];
    #pragma unroll
    for (int k = 0; k < 8; k++) acc2[k] = 0ull;
    #pragma unroll
    for (int d = 0; d < NIN; d++) {
        float zd = xi[ii*17 + d] * xj[jj*17 + d];
        ull zdup = packdup(zd);
        const ulonglong2* w = (const ulonglong2*)(Wa2 + d*16 + sh*8);
        #pragma unroll
        for (int k4 = 0; k4 < 4; k4++) {
            ulonglong2 ww = w[k4];
            acc2[2*k4]   = ffma2(zdup, ww.x, acc2[2*k4]);
            acc2[2*k4+1] = ffma2(zdup, ww.y, acc2[2*k4+1]);
        }
    }
    #pragma unroll
    for (int k = 0; k < 8; k++) {
        float2 m = unpackf2(acc2[k]);
        int s0 = sb + 2*k, s1 = s0 + 1;
        float e0 = dgflag ? dgs[ii*NH + s0] : 0.f;
        float e1 = dgflag ? dgs[ii*NH + s1] : 0.f;
        float t0 = t1s[s0], t1v = t1s[s1];
        float c1lo = fmaxf(m.x + posI[ii*NH + s0] + t0 + e0, 0.f);
        float c1hi = fmaxf(m.y + posI[ii*NH + s1] + t1v + e1, 0.f);
        float c2lo = fmaxf(m.x + posJ[jj*NH + s0] + t0 + e0, 0.f);
        float c2hi = fmaxf(m.y + posJ[jj*NH + s1] + t1v + e1, 0.f);
        apS[p*17 + sh*8 + k] = f2bf(c1lo + c2lo, c1hi + c2hi);
        amS[p*17 + sh*8 + k] = f2bf(c1lo - c2lo, c1hi - c2hi);
    }
    __syncthreads();

    // ---- rowsum partials + diag (from SMEM pair form) ----
    {
        int r = t >> 5, s = t & 31;       // 512 entries
        int w16 = s >> 1, hi = s & 1;
        // side I: sum over jj of c1 = 0.5*(ap+am)
        float vI = 0.f;
        #pragma unroll
        for (int q = 0; q < 16; q++) {
            float2 fa = bf2f(apS[(r*16 + q)*17 + w16]);
            float2 fm = bf2f(amS[(r*16 + q)*17 + w16]);
            vI += hi ? (fa.y + fm.y) : (fa.x + fm.x);
        }
        g_rowpart[(size_t)bid*1024 + t] = 0.5f*vI;
        // side J: sum over ii of c2 = 0.5*(ap-am)
        float vJ = 0.f;
        #pragma unroll
        for (int q = 0; q < 16; q++) {
            float2 fa = bf2f(apS[(q*16 + r)*17 + w16]);
            float2 fm = bf2f(amS[(q*16 + r)*17 + w16]);
            vJ += hi ? (fa.y - fm.y) : (fa.x - fm.x);
        }
        g_rowpart[(size_t)bid*1024 + 512 + t] = 0.5f*vJ;
        if (isdiag) {
            float2 fa = bf2f(apS[(r*16 + r)*17 + w16]);
            float2 fm = bf2f(amS[(r*16 + r)*17 + w16]);
            float dv = hi ? (fa.y + fm.y) : (fa.x + fm.x);
            g_diag[((size_t)b*NN + I + r)*NH + s] = 0.5f*dv;
        }
    }

    // ---- phase 2: layer-2 GEMM (16 s-values per thread) ----
    ull aP[8], aM[8];
    #pragma unroll
    for (int k = 0; k < 8; k++) { aP[k] = 0ull; aM[k] = 0ull; }
    const unsigned int* pa = apS + p*17;
    const unsigned int* ma = amS + p*17;
    #pragma unroll 4
    for (int w16 = 0; w16 < 16; w16++) {
        float2 fa = bf2f(pa[w16]);
        float2 fm = bf2f(ma[w16]);
        #pragma unroll
        for (int h = 0; h < 2; h++) {
            int tt = 2*w16 + h;
            ull xp = packdup(h ? fa.y : fa.x);
            ull xm = packdup(h ? fm.y : fm.x);
            const ulonglong2* wp = (const ulonglong2*)(Wp2 + tt*16 + sh*8);
            const ulonglong2* wm = (const ulonglong2*)(Wm2 + tt*16 + sh*8);
            #pragma unroll
            for (int q = 0; q < 4; q++) {
                ulonglong2 wwp = wp[q];
                aP[2*q]   = ffma2(xp, wwp.x, aP[2*q]);
                aP[2*q+1] = ffma2(xp, wwp.y, aP[2*q+1]);
                ulonglong2 wwm = wm[q];
                aM[2*q]   = ffma2(xm, wwm.x, aM[2*q]);
                aM[2*q+1] = ffma2(xm, wwm.y, aM[2*q+1]);
            }
        }
    }
    {
        unsigned int o1[8], o2[8];
        #pragma unroll
        for (int k = 0; k < 8; k++) {
            float2 P = unpackf2(aP[k]), M = unpackf2(aM[k]);
            o1[k] = f2bf(0.5f*(P.x + M.x), 0.5f*(P.y + M.y));
            o2[k] = f2bf(0.5f*(P.x - M.x), 0.5f*(P.y - M.y));
        }
        size_t off = ((size_t)bid*256 + p)*NH + sb;
        uint4* d1 = (uint4*)(g_G1 + off);
        d1[0] = make_uint4(o1[0], o1[1], o1[2], o1[3]);
        d1[1] = make_uint4(o1[4], o1[5], o1[6], o1[7]);
        uint4* d2 = (uint4*)(g_G2 + off);
        d2[0] = make_uint4(o2[0], o2[1], o2[2], o2[3]);
        d2[1] = make_uint4(o2[4], o2[5], o2[6], o2[7]);
    }
}

// ============================================================
// P2: parallel rowsum gather + layer-2 positional terms. grid (NT, NB).
// ============================================================
__global__ void __launch_bounds__(256) p2_kernel(const float* __restrict__ W2) {
    int ti = blockIdx.x, b = blockIdx.y, t = threadIdx.x;
    __shared__ float Ws3[NH*NH], Ws2s[NH*NH];
    __shared__ float raS[16*33], dvS[16*33];

    for (int e = t; e < NH*NH; e += 256) {
        Ws3[e]  = W2[e*5 + 3];
        Ws2s[e] = W2[e*5 + 2];
    }

    int ii = t >> 4, sp = t & 15;
    float2 acc = make_float2(0.f, 0.f);
    for (int tj = ti; tj < NT; tj++) {
        int tp = ti*NT - ti*(ti-1)/2 + (tj - ti);
        float2 v = *(const float2*)(g_rowpart + (size_t)(b*NTRI + tp)*1024 + ii*NH + 2*sp);
        acc.x += v.x; acc.y += v.y;
    }
    for (int tk = 0; tk < ti; tk++) {
        int tp = tk*NT - tk*(tk-1)/2 + (ti - tk);
        float2 v = *(const float2*)(g_rowpart + (size_t)(b*NTRI + tp)*1024 + 512 + ii*NH + 2*sp);
        acc.x += v.x; acc.y += v.y;
    }
    raS[ii*33 + 2*sp] = acc.x; raS[ii*33 + 2*sp + 1] = acc.y;
    {
        float2 dv = *(const float2*)(g_diag + ((size_t)b*NN + ti*16 + ii)*NH + 2*sp);
        dvS[ii*33 + 2*sp] = dv.x; dvS[ii*33 + 2*sp + 1] = dv.y;
    }
    __syncthreads();

    if (t < NH) {
        float s = 0.f;
        #pragma unroll
        for (int r = 0; r < 16; r++) s += raS[r*33 + t];
        g_totp[(b*NT + ti)*NH + t] = s;
    }

    const float inv_n = 1.0f/(float)NN;
    int s0 = t & 15;
    float r2a = 0.f, r2b = 0.f, d2a = 0.f, d2b = 0.f;
    #pragma unroll
    for (int q = 0; q < NH; q++) {
        float rq = raS[ii*33 + q]*inv_n;
        float dq = dvS[ii*33 + q];
        r2a = fmaf(rq, Ws3[q*NH + s0],      r2a);
        r2b = fmaf(rq, Ws3[q*NH + s0 + 16], r2b);
        d2a = fmaf(dq, Ws2s[q*NH + s0],      d2a);
        d2b = fmaf(dq, Ws2s[q*NH + s0 + 16], d2b);
    }
    size_t ro = ((size_t)b*NN + ti*16 + ii)*NH;
    g_R2 [ro + s0]      = r2a;
    g_R2 [ro + s0 + 16] = r2b;
    g_Dg2[ro + s0]      = d2a;
    g_Dg2[ro + s0 + 16] = d2b;
}

// ============================================================
// P2T: total-sum term T2 (8 blocks x 32 threads).
// ============================================================
__global__ void __launch_bounds__(32) p2t_kernel(const float* __restrict__ W2,
                                                 const float* __restrict__ b2) {
    int b = blockIdx.x, t = threadIdx.x;
    __shared__ float tots[NH];
    float s = 0.f;
    #pragma unroll
    for (int k = 0; k < NT; k++) s += g_totp[(b*NT + k)*NH + t];
    tots[t] = s * (1.0f/((float)NN*(float)NN));
    __syncwarp();
    float t2 = b2[t];
    #pragma unroll
    for (int q = 0; q < NH; q++) t2 = fmaf(tots[q], W2[(q*NH + t)*5 + 4], t2);
    g_T2[b*NH + t] = t2;
}

// ============================================================
// K2B: streaming epilogue — load G1/G2, add positional, relu, reduce.
// ============================================================
__global__ void __launch_bounds__(256) k2b_kernel() {
    __shared__ float bs1[512], bs2[512], dgI[512];
    __shared__ float red[256*36];
    __shared__ float part2[8*NH];

    int tp = blockIdx.x, b = blockIdx.y, t = threadIdx.x;
    int ti = 0, rr0 = tp;
    while (rr0 >= NT - ti) { rr0 -= NT - ti; ti++; }
    int tj = ti + rr0;
    int I = ti*TILE, J = tj*TILE;
    int bid = b*NTRI + tp;
    bool isdiag = (ti == tj);

    for (int e = t; e < 512; e += 256) {
        int r = e >> 5, s = e & 31;
        float t2v = g_T2[b*NH + s];
        bs1[e] = g_R2[((size_t)b*NN + I + r)*NH + s] + t2v;
        bs2[e] = g_R2[((size_t)b*NN + J + r)*NH + s] + t2v;
        dgI[e] = g_Dg2[((size_t)b*NN + I + r)*NH + s];
    }
    __syncthreads();

    int ii = t >> 4, jj = t & 15;
    size_t off = ((size_t)bid*256 + t)*NH;
    const uint4* q1 = (const uint4*)(g_G1 + off);
    const uint4* q2 = (const uint4*)(g_G2 + off);

    float cs[NH];
    #pragma unroll
    for (int v4 = 0; v4 < 4; v4++) {
        uint4 a = q1[v4], bq = q2[v4];
        unsigned int ua[4] = {a.x, a.y, a.z, a.w};
        unsigned int ub[4] = {bq.x, bq.y, bq.z, bq.w};
        #pragma unroll
        for (int u = 0; u < 4; u++) {
            int s0 = v4*8 + 2*u;
            float2 f1 = bf2f(ua[u]);
            float2 f2 = bf2f(ub[u]);
            #pragma unroll
            for (int h = 0; h < 2; h++) {
                int s = s0 + h;
                float g1 = h ? f1.y : f1.x;
                float g2 = h ? f2.y : f2.x;
                float b1v = bs1[ii*NH + s];
                if (isdiag && ii == jj) b1v += dgI[ii*NH + s];
                float c1 = fmaxf(g1 + b1v, 0.f);
                float c2 = fmaxf(g2 + bs2[jj*NH + s], 0.f);
                float v = c1 + c2;
                if (isdiag) v = (ii < jj) ? (c1 + c2) : ((ii == jj) ? c1 : 0.f);
                cs[s] = v;
            }
        }
    }

    {
        float4* rr = (float4*)(red + t*36);
        #pragma unroll
        for (int k = 0; k < 8; k++)
            rr[k] = make_float4(cs[4*k], cs[4*k+1], cs[4*k+2], cs[4*k+3]);
    }
    __syncthreads();
    {
        int s = t & 31, c = t >> 5;
        float tsum = 0.f;
        #pragma unroll
        for (int r = 0; r < 32; r++) tsum += red[(c*32 + r)*36 + s];
        part2[c*NH + s] = tsum;
    }
    __syncthreads();
    if (t < NH) {
        float p = 0.f;
        #pragma unroll
        for (int c = 0; c < 8; c++) p += part2[c*NH + t];
        g_part[(size_t)bid*NH + t] = p;
    }
}

// ============================================================
// Final: parallel partial reduce + MLP 32->128->128->1.
// ============================================================
__global__ void __launch_bounds__(256) fin_kernel(const float* __restrict__ D1,
                                                  const float* __restrict__ db1,
                                                  const float* __restrict__ D2,
                                                  const float* __restrict__ db2,
                                                  const float* __restrict__ D3,
                                                  const float* __restrict__ db3,
                                                  float* __restrict__ out) {
    int b = blockIdx.x, tid = threadIdx.x;
    __shared__ float pp[8*NH];
    __shared__ float p[NH];
    __shared__ float m1[128];
    __shared__ float h2p[256];
    __shared__ float m2[128];
    __shared__ float wr[4];

    {
        int s = tid & 31, c = tid >> 5;
        float a = 0.f;
        #pragma unroll 4
        for (int k = c; k < NTRI; k += 8) a += g_part[(size_t)(b*NTRI + k)*NH + s];
        pp[tid] = a;
    }
    __syncthreads();
    if (tid < NH) {
        float t = 0.f;
        #pragma unroll
        for (int c = 0; c < 8; c++) t += pp[c*NH + tid];
        p[tid] = fmaxf(t, 0.f);
    }
    __syncthreads();
    if (tid < 128) {
        float a = db1[tid];
        #pragma unroll
        for (int q = 0; q < NH; q++) a = fmaf(p[q], D1[q*128 + tid], a);
        m1[tid] = fmaxf(a, 0.f);
    }
    __syncthreads();
    {
        int o = tid & 127, half = tid >> 7;
        float a = 0.f;
        #pragma unroll 16
        for (int e = half*64; e < half*64 + 64; e++)
            a = fmaf(m1[e], D2[e*128 + o], a);
        h2p[tid] = a;
    }
    __syncthreads();
    if (tid < 128) m2[tid] = fmaxf(h2p[tid] + h2p[128 + tid] + db2[tid], 0.f);
    __syncthreads();
    if (tid < 128) {
        float v = m2[tid] * D3[tid];
        #pragma unroll
        for (int o = 16; o; o >>= 1) v += __shfl_xor_sync(0xffffffffu, v, o);
        if ((tid & 31) == 0) wr[tid >> 5] = v;
    }
    __syncthreads();
    if (tid == 0) out[b] = wr[0] + wr[1] + wr[2] + wr[3] + db3[0];
}

extern "C" void kernel_launch(void* const* d_in, const int* in_sizes, int n_in,
                              void* d_out, int out_size) {
    const float* x   = (const float*)d_in[0];
    const float* W1  = (const float*)d_in[1];
    const float* b1  = (const float*)d_in[2];
    const float* W2  = (const float*)d_in[3];
    const float* b2  = (const float*)d_in[4];
    const float* D1  = (const float*)d_in[5];
    const float* db1 = (const float*)d_in[6];
    const float* D2  = (const float*)d_in[7];
    const float* db2 = (const float*)d_in[8];
    const float* D3  = (const float*)d_in[9];
    const float* db3 = (const float*)d_in[10];
    float* out = (float*)d_out;

    size_t k1f_smem = 53504;
    cudaFuncSetAttribute(k1f_kernel, cudaFuncAttributeMaxDynamicSharedMemorySize,
                         (int)k1f_smem);

    p1_kernel<<<NB, 256>>>(x, W1, b1);
    k1f_kernel<<<dim3(NTRI, NB), 512, k1f_smem>>>(x, W1, W2);
    p2_kernel<<<dim3(NT, NB), 256>>>(W2);
    p2t_kernel<<<NB, 32>>>(W2, b2);
    k2b_kernel<<<dim3(NTRI, NB), 256>>>();
    fin_kernel<<<NB, 256>>>(D1, db1, D2, db2, D3, db3, out);
}